// round 8
// baseline (speedup 1.0000x reference)
#include <cuda_runtime.h>
#include <cuda_bf16.h>
#include <cstdint>

#define OBSD 128
#define ACTD 32
#define HIDD 256
#define NP   64
#define NB   4096
#define MT   32
#define EPSV 1e-5f

// ---------------- SMEM layout (bytes) ----------------
#define AFRAG_HI 0          // 2 mtiles x 16 ktiles x 32 lanes x 16B = 16KB
#define AFRAG_LO 16384
#define PAR0_OFF 32768      // 768 floats
#define PAR1_OFF 35840      // 768 floats
#define RED1_OFF 38912      // 128 floats
#define RED2_OFF 39424      // 128 floats
#define DSMEM_BYTES 39936

// ---------------- weight fragment image ----------------
#define L1_BYTES ((size_t)OBSD*HIDD*4)   // per-policy bytes (hi+lo bf16 = 4B/elem)
#define L2_BYTES ((size_t)HIDD*HIDD*4)
#define L4_BYTES ((size_t)HIDD*ACTD*4)
#define OFF_L1 0ull
#define OFF_L2 (OFF_L1 + 64ull*L1_BYTES)
#define OFF_L3 (OFF_L2 + 64ull*L2_BYTES)
#define OFF_L4 (OFF_L3 + 64ull*L2_BYTES)
#define WIMG_TOTAL (OFF_L4 + 64ull*L4_BYTES)

__device__ __align__(128) unsigned char g_wimg[WIMG_TOTAL];

// ---------------- helpers ----------------
__device__ __forceinline__ void mma16816(float* c, const uint4& a, uint32_t b0, uint32_t b1) {
    asm volatile(
        "mma.sync.aligned.m16n8k16.row.col.f32.bf16.bf16.f32 "
        "{%0,%1,%2,%3}, {%4,%5,%6,%7}, {%8,%9}, {%0,%1,%2,%3};"
        : "+f"(c[0]), "+f"(c[1]), "+f"(c[2]), "+f"(c[3])
        : "r"(a.x), "r"(a.y), "r"(a.z), "r"(a.w), "r"(b0), "r"(b1));
}

// packed split: hp = bf16x2{lo=y0, hi=y1}; lp = residuals, same order
__device__ __forceinline__ void split_pack(float y0, float y1, uint32_t& hp, uint32_t& lp) {
    asm("cvt.rn.bf16x2.f32 %0, %2, %1;" : "=r"(hp) : "f"(y0), "f"(y1));
    float f0 = __uint_as_float(hp << 16);
    float f1 = __uint_as_float(hp & 0xffff0000u);
    float r0 = y0 - f0, r1 = y1 - f1;
    asm("cvt.rn.bf16x2.f32 %0, %2, %1;" : "=r"(lp) : "f"(r0), "f"(r1));
}

__device__ __forceinline__ float elu1(float y) { return y > 0.f ? y : (__expf(y) - 1.f); }

// ---------------- weight preprocess (merged: one kernel, z = layer) ----------------
template<int N, int K>
__device__ __forceinline__ void prep_dev(const float* __restrict__ W, size_t off, float* tile)
{
    const int p = blockIdx.x, kt = blockIdx.y;
    if (kt >= K / 16) return;
    const int tid = threadIdx.x;
    const float4* src = reinterpret_cast<const float4*>(W + ((size_t)p * K + (size_t)kt * 16) * N);
    constexpr int NL4 = 16 * N / 4;
    for (int i = tid; i < NL4; i += 256)
        reinterpret_cast<float4*>(tile)[i] = src[i];
    __syncthreads();
    constexpr int NT = N / 8;
    uint4* dst = reinterpret_cast<uint4*>(g_wimg + off + (size_t)p * ((size_t)K * N * 4));
    for (int u = tid; u < NT * 32; u += 256) {
        int nt = u >> 5, lane = u & 31;
        int n = nt * 8 + (lane >> 2), q = (lane & 3) * 2;
        uint32_t hp[2], lp[2];
#pragma unroll
        for (int r = 0; r < 2; r++) {
            float w0 = tile[(q + 8 * r) * N + n];
            float w1 = tile[(q + 8 * r + 1) * N + n];
            split_pack(w0, w1, hp[r], lp[r]);
        }
        uint4 v; v.x = hp[0]; v.y = hp[1]; v.z = lp[0]; v.w = lp[1];
        dst[((size_t)kt * NT + nt) * 32 + lane] = v;
    }
}

__global__ void prep_all_kernel(const float* __restrict__ W1, const float* __restrict__ W2,
                                const float* __restrict__ W3, const float* __restrict__ W4)
{
    __shared__ float tile[16 * HIDD];
    switch (blockIdx.z) {
        case 0: prep_dev<HIDD, OBSD>(W1, OFF_L1, tile); break;
        case 1: prep_dev<HIDD, HIDD>(W2, OFF_L2, tile); break;
        case 2: prep_dev<HIDD, HIDD>(W3, OFF_L3, tile); break;
        default: prep_dev<ACTD, HIDD>(W4, OFF_L4, tile); break;
    }
}

// ---------------- fused main kernel ----------------
// A-fragment smem layout (MT=32): idx(m,k) -> uint32 slot
//   mtile=m/16 (0..1), ktile=k/16, a_lane=(m%8)*4+((k%8)/2), r=2*((k%16)>=8)+((m%16)>=8)
//   idx = ((mtile*16 + ktile)*32 + a_lane)*4 + r
// 4 warps: warp wn owns cols [wn*64, wn*64+64), computes both mtiles (32 rows).

template<int K, bool ACT, int NEXTN>
__device__ __forceinline__ void hidden_layer(
    unsigned char* smem, const uint4* __restrict__ bfr,
    const float* __restrict__ nb, const float* __restrict__ ng, const float* __restrict__ nbe,
    const float* parC, float* parN, int tid)
{
    const int lane = tid & 31;
    const int wn   = tid >> 5;      // 0..3
    uint32_t* ah = reinterpret_cast<uint32_t*>(smem + AFRAG_HI);
    uint32_t* al = reinterpret_cast<uint32_t*>(smem + AFRAG_LO);
    float* red1 = reinterpret_cast<float*>(smem + RED1_OFF);
    float* red2 = reinterpret_cast<float*>(smem + RED2_OFF);
    const uint4* ah4 = reinterpret_cast<const uint4*>(ah);
    const uint4* al4 = reinterpret_cast<const uint4*>(al);

    float acc[2][8][4];
#pragma unroll
    for (int mt = 0; mt < 2; mt++)
#pragma unroll
        for (int j = 0; j < 8; j++)
#pragma unroll
            for (int r = 0; r < 4; r++) acc[mt][j][r] = 0.f;

    const uint4* bwarp = bfr + (size_t)wn * 8 * 32 + lane;  // + kt*1024 + j*32
    constexpr int KTN = K / 16;

#pragma unroll 1
    for (int kt = 0; kt < KTN; kt++) {
        uint4 Ah[2], Al[2];
#pragma unroll
        for (int mt = 0; mt < 2; mt++) {
            Ah[mt] = ah4[(mt * 16 + kt) * 32 + lane];
            Al[mt] = al4[(mt * 16 + kt) * 32 + lane];
        }
        // batch 0: nt 0..3
        {
            uint4 B[4];
#pragma unroll
            for (int j = 0; j < 4; j++)
                B[j] = __ldg(bwarp + (size_t)kt * 1024 + j * 32);
#pragma unroll
            for (int mt = 0; mt < 2; mt++)
#pragma unroll
                for (int j = 0; j < 4; j++) {
                    mma16816(acc[mt][j], Ah[mt], B[j].x, B[j].y);
                    mma16816(acc[mt][j], Ah[mt], B[j].z, B[j].w);
                    mma16816(acc[mt][j], Al[mt], B[j].x, B[j].y);
                }
        }
        // batch 1: nt 4..7
        {
            uint4 B[4];
#pragma unroll
            for (int j = 0; j < 4; j++)
                B[j] = __ldg(bwarp + (size_t)kt * 1024 + (j + 4) * 32);
#pragma unroll
            for (int mt = 0; mt < 2; mt++)
#pragma unroll
                for (int j = 0; j < 4; j++) {
                    mma16816(acc[mt][j + 4], Ah[mt], B[j].x, B[j].y);
                    mma16816(acc[mt][j + 4], Ah[mt], B[j].z, B[j].w);
                    mma16816(acc[mt][j + 4], Al[mt], B[j].x, B[j].y);
                }
        }
    }

    // P1: stage next layer's params + bias + per-row partial sums
    for (int i = tid; i < 3 * NEXTN; i += 128)
        parN[i] = (i < NEXTN) ? nb[i] : (i < 2 * NEXTN ? ng[i - NEXTN] : nbe[i - 2 * NEXTN]);

#pragma unroll
    for (int mt = 0; mt < 2; mt++) {
        float s1a = 0.f, s2a = 0.f, s1b = 0.f, s2b = 0.f;
#pragma unroll
        for (int j = 0; j < 8; j++) {
            int n0 = wn * 64 + j * 8 + (lane & 3) * 2;
            float b0 = parC[n0], b1 = parC[n0 + 1];
            float y0 = acc[mt][j][0] + b0, y1 = acc[mt][j][1] + b1;
            float y2 = acc[mt][j][2] + b0, y3 = acc[mt][j][3] + b1;
            acc[mt][j][0] = y0; acc[mt][j][1] = y1;
            acc[mt][j][2] = y2; acc[mt][j][3] = y3;
            s1a += y0 + y1; s2a = fmaf(y0, y0, fmaf(y1, y1, s2a));
            s1b += y2 + y3; s2b = fmaf(y2, y2, fmaf(y3, y3, s2b));
        }
        s1a += __shfl_xor_sync(~0u, s1a, 1); s1a += __shfl_xor_sync(~0u, s1a, 2);
        s2a += __shfl_xor_sync(~0u, s2a, 1); s2a += __shfl_xor_sync(~0u, s2a, 2);
        s1b += __shfl_xor_sync(~0u, s1b, 1); s1b += __shfl_xor_sync(~0u, s1b, 2);
        s2b += __shfl_xor_sync(~0u, s2b, 1); s2b += __shfl_xor_sync(~0u, s2b, 2);
        if ((lane & 3) == 0) {
            int m0 = mt * 16 + (lane >> 2);
            red1[wn * 32 + m0]     = s1a; red2[wn * 32 + m0]     = s2a;
            red1[wn * 32 + m0 + 8] = s1b; red2[wn * 32 + m0 + 8] = s2b;
        }
    }
    __syncthreads();

    // stats: one warp, one row per thread
    if (tid < 32) {
        float t1 = red1[tid] + red1[32 + tid] + red1[64 + tid] + red1[96 + tid];
        float t2 = red2[tid] + red2[32 + tid] + red2[64 + tid] + red2[96 + tid];
        float mean = t1 * (1.f / 256.f);
        float var  = fmaf(-mean, mean, t2 * (1.f / 256.f));
        float rstd = rsqrtf(var + EPSV);
        red1[tid] = mean; red2[tid] = rstd;
    }
    __syncthreads();

    // P3: normalize + activation + write next layer's A-fragments
#pragma unroll
    for (int mt = 0; mt < 2; mt++) {
        int mA = mt * 16 + (lane >> 2);
        float meanA = red1[mA],     rstdA = red2[mA];
        float meanB = red1[mA + 8], rstdB = red2[mA + 8];
#pragma unroll
        for (int j = 0; j < 8; j++) {
            int n0 = wn * 64 + j * 8 + (lane & 3) * 2;
            float g0 = parC[256 + n0], g1 = parC[257 + n0];
            float e0 = parC[512 + n0], e1 = parC[513 + n0];
            float y0 = fmaf((acc[mt][j][0] - meanA) * rstdA, g0, e0);
            float y1 = fmaf((acc[mt][j][1] - meanA) * rstdA, g1, e1);
            float y2 = fmaf((acc[mt][j][2] - meanB) * rstdB, g0, e0);
            float y3 = fmaf((acc[mt][j][3] - meanB) * rstdB, g1, e1);
            if (ACT) { y0 = elu1(y0); y1 = elu1(y1); y2 = elu1(y2); y3 = elu1(y3); }
            int aln = ((lane >> 2) << 2) + ((n0 & 7) >> 1);
            int rA  = ((n0 & 15) >= 8) ? 2 : 0;
            int idxb = ((mt * 16 + (n0 >> 4)) * 32 + aln) * 4 + rA;
            uint32_t hp0, lp0, hp1, lp1;
            split_pack(y0, y1, hp0, lp0);
            split_pack(y2, y3, hp1, lp1);
            *reinterpret_cast<uint2*>(ah + idxb) = make_uint2(hp0, hp1);
            *reinterpret_cast<uint2*>(al + idxb) = make_uint2(lp0, lp1);
        }
    }
    __syncthreads();
}

// final layer: K=256, N=32, 32 rows. warp w: mtile = w&1, nt-half = w>>1.
__device__ __forceinline__ void final_layer(
    unsigned char* smem, const uint4* __restrict__ bfr,
    const float* parC, float* __restrict__ out, int r0, int p, int tid)
{
    const int lane = tid & 31, wid = tid >> 5;
    const int m = wid & 1, nth = wid >> 1;
    const uint4* ah4 = reinterpret_cast<const uint4*>(smem + AFRAG_HI);
    const uint4* al4 = reinterpret_cast<const uint4*>(smem + AFRAG_LO);
    float* red1 = reinterpret_cast<float*>(smem + RED1_OFF);
    float* red2 = reinterpret_cast<float*>(smem + RED2_OFF);

    float acc[2][4];
#pragma unroll
    for (int j = 0; j < 2; j++)
#pragma unroll
        for (int r = 0; r < 4; r++) acc[j][r] = 0.f;

#pragma unroll 1
    for (int kt = 0; kt < 16; kt++) {
        uint4 B[2];
#pragma unroll
        for (int j = 0; j < 2; j++)
            B[j] = __ldg(&bfr[((size_t)kt * 4 + nth * 2 + j) * 32 + lane]);
        uint4 Ah = ah4[(m * 16 + kt) * 32 + lane];
        uint4 Al = al4[(m * 16 + kt) * 32 + lane];
#pragma unroll
        for (int j = 0; j < 2; j++) {
            mma16816(acc[j], Ah, B[j].x, B[j].y);
            mma16816(acc[j], Ah, B[j].z, B[j].w);
            mma16816(acc[j], Al, B[j].x, B[j].y);
        }
    }

    // bias + partial sums over this warp's 16-col slice
    float s1a = 0.f, s2a = 0.f, s1b = 0.f, s2b = 0.f;
#pragma unroll
    for (int j = 0; j < 2; j++) {
        int n0 = nth * 16 + j * 8 + (lane & 3) * 2;
        float b0 = parC[n0], b1 = parC[n0 + 1];
        float y0 = acc[j][0] + b0, y1 = acc[j][1] + b1;
        float y2 = acc[j][2] + b0, y3 = acc[j][3] + b1;
        acc[j][0] = y0; acc[j][1] = y1; acc[j][2] = y2; acc[j][3] = y3;
        s1a += y0 + y1; s2a = fmaf(y0, y0, fmaf(y1, y1, s2a));
        s1b += y2 + y3; s2b = fmaf(y2, y2, fmaf(y3, y3, s2b));
    }
    s1a += __shfl_xor_sync(~0u, s1a, 1); s1a += __shfl_xor_sync(~0u, s1a, 2);
    s2a += __shfl_xor_sync(~0u, s2a, 1); s2a += __shfl_xor_sync(~0u, s2a, 2);
    s1b += __shfl_xor_sync(~0u, s1b, 1); s1b += __shfl_xor_sync(~0u, s1b, 2);
    s2b += __shfl_xor_sync(~0u, s2b, 1); s2b += __shfl_xor_sync(~0u, s2b, 2);
    if ((lane & 3) == 0) {
        int base = (m * 2 + nth) * 16 + (lane >> 2);
        red1[base] = s1a; red2[base] = s2a;
        red1[base + 8] = s1b; red2[base + 8] = s2b;
    }
    __syncthreads();

    // combine nt-halves; each warp computes stats for its rows (redundant across nth)
    const int r = lane >> 2;
    float t1A = red1[(m * 2) * 16 + r]     + red1[(m * 2 + 1) * 16 + r];
    float t2A = red2[(m * 2) * 16 + r]     + red2[(m * 2 + 1) * 16 + r];
    float t1B = red1[(m * 2) * 16 + r + 8] + red1[(m * 2 + 1) * 16 + r + 8];
    float t2B = red2[(m * 2) * 16 + r + 8] + red2[(m * 2 + 1) * 16 + r + 8];
    const float meanA = t1A * (1.f / 32.f);
    const float rstdA = rsqrtf(fmaf(-meanA, meanA, t2A * (1.f / 32.f)) + EPSV);
    const float meanB = t1B * (1.f / 32.f);
    const float rstdB = rsqrtf(fmaf(-meanB, meanB, t2B * (1.f / 32.f)) + EPSV);

    const int mA = m * 16 + r;
#pragma unroll
    for (int j = 0; j < 2; j++) {
        int n0 = nth * 16 + j * 8 + (lane & 3) * 2;
        float g0 = parC[32 + n0], g1 = parC[33 + n0];
        float e0 = parC[64 + n0], e1 = parC[65 + n0];
        float2 o;
        o.x = fmaf((acc[j][0] - meanA) * rstdA, g0, e0);
        o.y = fmaf((acc[j][1] - meanA) * rstdA, g1, e1);
        *reinterpret_cast<float2*>(out + (size_t)(r0 + mA) * (NP * ACTD) + p * ACTD + n0) = o;
        o.x = fmaf((acc[j][2] - meanB) * rstdB, g0, e0);
        o.y = fmaf((acc[j][3] - meanB) * rstdB, g1, e1);
        *reinterpret_cast<float2*>(out + (size_t)(r0 + mA + 8) * (NP * ACTD) + p * ACTD + n0) = o;
    }
}

__global__ __launch_bounds__(128, 4)
void mlp_fused_kernel(
    const float* __restrict__ obs,
    const float* __restrict__ b1, const float* __restrict__ g1, const float* __restrict__ be1,
    const float* __restrict__ b2, const float* __restrict__ g2, const float* __restrict__ be2,
    const float* __restrict__ b3, const float* __restrict__ g3, const float* __restrict__ be3,
    const float* __restrict__ b4, const float* __restrict__ g4, const float* __restrict__ be4,
    float* __restrict__ out)
{
    extern __shared__ unsigned char smem[];
    const int tid = threadIdx.x;
    const int p   = blockIdx.y;
    const int r0  = blockIdx.x * MT;
    uint32_t* ah = reinterpret_cast<uint32_t*>(smem + AFRAG_HI);
    uint32_t* al = reinterpret_cast<uint32_t*>(smem + AFRAG_LO);
    float* par0 = reinterpret_cast<float*>(smem + PAR0_OFF);
    float* par1 = reinterpret_cast<float*>(smem + PAR1_OFF);

    // stage observation tile as split-bf16 A-fragments + layer-1 params
    {
        const int m = tid >> 2, q4 = tid & 3;
        const float* orow = obs + (size_t)(r0 + m) * OBSD + q4 * 32;
#pragma unroll
        for (int j = 0; j < 16; j++) {
            float2 v = reinterpret_cast<const float2*>(orow)[j];
            uint32_t hp, lp; split_pack(v.x, v.y, hp, lp);
            int k = q4 * 32 + j * 2;
            int aln = ((m & 7) << 2) + ((k & 7) >> 1);
            int r = (((k & 15) >= 8) ? 2 : 0) + (((m & 15) >= 8) ? 1 : 0);
            int idx = (((m >> 4) * 16 + (k >> 4)) * 32 + aln) * 4 + r;
            ah[idx] = hp; al[idx] = lp;
        }
        const float* s1 = b1 + p * HIDD;
        const float* s2 = g1 + p * HIDD;
        const float* s3 = be1 + p * HIDD;
        for (int i = tid; i < 768; i += 128)
            par0[i] = (i < 256) ? s1[i] : (i < 512 ? s2[i - 256] : s3[i - 512]);
    }
    __syncthreads();

    hidden_layer<OBSD, true, HIDD>(smem,
        reinterpret_cast<const uint4*>(g_wimg + OFF_L1 + (size_t)p * L1_BYTES),
        b2 + p * HIDD, g2 + p * HIDD, be2 + p * HIDD, par0, par1, tid);
    hidden_layer<HIDD, true, HIDD>(smem,
        reinterpret_cast<const uint4*>(g_wimg + OFF_L2 + (size_t)p * L2_BYTES),
        b3 + p * HIDD, g3 + p * HIDD, be3 + p * HIDD, par1, par0, tid);
    hidden_layer<HIDD, true, ACTD>(smem,
        reinterpret_cast<const uint4*>(g_wimg + OFF_L3 + (size_t)p * L2_BYTES),
        b4 + p * ACTD, g4 + p * ACTD, be4 + p * ACTD, par0, par1, tid);
    final_layer(smem,
        reinterpret_cast<const uint4*>(g_wimg + OFF_L4 + (size_t)p * L4_BYTES),
        par1, out, r0, p, tid);
}

// ---------------- launch ----------------
extern "C" void kernel_launch(void* const* d_in, const int* in_sizes, int n_in,
                              void* d_out, int out_size)
{
    const float* obs = (const float*)d_in[0];
    const float* W1  = (const float*)d_in[1];
    const float* b1  = (const float*)d_in[2];
    const float* g1  = (const float*)d_in[3];
    const float* be1 = (const float*)d_in[4];
    const float* W2  = (const float*)d_in[5];
    const float* b2  = (const float*)d_in[6];
    const float* g2  = (const float*)d_in[7];
    const float* be2 = (const float*)d_in[8];
    const float* W3  = (const float*)d_in[9];
    const float* b3  = (const float*)d_in[10];
    const float* g3  = (const float*)d_in[11];
    const float* be3 = (const float*)d_in[12];
    const float* W4  = (const float*)d_in[13];
    const float* b4  = (const float*)d_in[14];
    const float* g4  = (const float*)d_in[15];
    const float* be4 = (const float*)d_in[16];
    float* out = (float*)d_out;

    prep_all_kernel<<<dim3(NP, HIDD / 16, 4), 256>>>(W1, W2, W3, W4);

    cudaFuncSetAttribute(mlp_fused_kernel,
                         cudaFuncAttributeMaxDynamicSharedMemorySize, DSMEM_BYTES);
    dim3 grid(NB / MT, NP);
    mlp_fused_kernel<<<grid, 128, DSMEM_BYTES>>>(
        obs, b1, g1, be1, b2, g2, be2, b3, g3, be3, b4, g4, be4, out);
}

// round 9
// speedup vs baseline: 1.0357x; 1.0357x over previous
#include <cuda_runtime.h>
#include <cuda_bf16.h>
#include <cstdint>

#define OBSD 128
#define ACTD 32
#define HIDD 256
#define NP   64
#define NB   4096
#define MT   64
#define EPSV 1e-5f

// ---------------- SMEM layout (bytes) ----------------
#define AFRAG_HI 0          // 4 mtiles x 16 ktiles x 32 lanes x 16B = 32KB
#define AFRAG_LO 32768
#define PAR0_OFF 65536      // 768 floats
#define PAR1_OFF 68608      // 768 floats
#define RED1_OFF 71680      // 8*64 floats
#define RED2_OFF 73728      // 8*64 floats
#define DSMEM_BYTES 75776

// ---------------- weight fragment image ----------------
#define L1_BYTES ((size_t)OBSD*HIDD*4)
#define L2_BYTES ((size_t)HIDD*HIDD*4)
#define L4_BYTES ((size_t)HIDD*ACTD*4)
#define OFF_L1 0ull
#define OFF_L2 (OFF_L1 + 64ull*L1_BYTES)
#define OFF_L3 (OFF_L2 + 64ull*L2_BYTES)
#define OFF_L4 (OFF_L3 + 64ull*L2_BYTES)
#define WIMG_TOTAL (OFF_L4 + 64ull*L4_BYTES)

__device__ __align__(128) unsigned char g_wimg[WIMG_TOTAL];

// ---------------- helpers ----------------
__device__ __forceinline__ void mma16816(float* c, const uint4& a, uint32_t b0, uint32_t b1) {
    asm volatile(
        "mma.sync.aligned.m16n8k16.row.col.f32.bf16.bf16.f32 "
        "{%0,%1,%2,%3}, {%4,%5,%6,%7}, {%8,%9}, {%0,%1,%2,%3};"
        : "+f"(c[0]), "+f"(c[1]), "+f"(c[2]), "+f"(c[3])
        : "r"(a.x), "r"(a.y), "r"(a.z), "r"(a.w), "r"(b0), "r"(b1));
}

// packed split: hp = bf16x2{lo=y0, hi=y1}; lp = residuals, same order
__device__ __forceinline__ void split_pack(float y0, float y1, uint32_t& hp, uint32_t& lp) {
    asm("cvt.rn.bf16x2.f32 %0, %2, %1;" : "=r"(hp) : "f"(y0), "f"(y1));
    float f0 = __uint_as_float(hp << 16);
    float f1 = __uint_as_float(hp & 0xffff0000u);
    float r0 = y0 - f0, r1 = y1 - f1;
    asm("cvt.rn.bf16x2.f32 %0, %2, %1;" : "=r"(lp) : "f"(r0), "f"(r1));
}

__device__ __forceinline__ float elu1(float y) { return y > 0.f ? y : (__expf(y) - 1.f); }

// ---------------- weight preprocess (merged, validated) ----------------
template<int N, int K>
__device__ __forceinline__ void prep_dev(const float* __restrict__ W, size_t off, float* tile)
{
    const int p = blockIdx.x, kt = blockIdx.y;
    if (kt >= K / 16) return;
    const int tid = threadIdx.x;
    const float4* src = reinterpret_cast<const float4*>(W + ((size_t)p * K + (size_t)kt * 16) * N);
    constexpr int NL4 = 16 * N / 4;
    for (int i = tid; i < NL4; i += 256)
        reinterpret_cast<float4*>(tile)[i] = src[i];
    __syncthreads();
    constexpr int NT = N / 8;
    uint4* dst = reinterpret_cast<uint4*>(g_wimg + off + (size_t)p * ((size_t)K * N * 4));
    for (int u = tid; u < NT * 32; u += 256) {
        int nt = u >> 5, lane = u & 31;
        int n = nt * 8 + (lane >> 2), q = (lane & 3) * 2;
        uint32_t hp[2], lp[2];
#pragma unroll
        for (int r = 0; r < 2; r++) {
            float w0 = tile[(q + 8 * r) * N + n];
            float w1 = tile[(q + 8 * r + 1) * N + n];
            split_pack(w0, w1, hp[r], lp[r]);
        }
        uint4 v; v.x = hp[0]; v.y = hp[1]; v.z = lp[0]; v.w = lp[1];
        dst[((size_t)kt * NT + nt) * 32 + lane] = v;
    }
}

__global__ void prep_all_kernel(const float* __restrict__ W1, const float* __restrict__ W2,
                                const float* __restrict__ W3, const float* __restrict__ W4)
{
    __shared__ float tile[16 * HIDD];
    switch (blockIdx.z) {
        case 0: prep_dev<HIDD, OBSD>(W1, OFF_L1, tile); break;
        case 1: prep_dev<HIDD, HIDD>(W2, OFF_L2, tile); break;
        case 2: prep_dev<HIDD, HIDD>(W3, OFF_L3, tile); break;
        default: prep_dev<ACTD, HIDD>(W4, OFF_L4, tile); break;
    }
}

// ---------------- fused main kernel ----------------
// A-fragment smem layout: idx(m,k) -> uint32 slot (m in [0,64))
//   mtile=m/16, ktile=k/16, a_lane=(m%8)*4+((k%8)/2), r=2*((k%16)>=8)+((m%16)>=8)
//   idx = ((mtile*16 + ktile)*32 + a_lane)*4 + r
// 8 warps: warp wn owns cols [wn*32, wn*32+32), computes all 4 mtiles (64 rows).

template<int K, bool ACT, int NEXTN>
__device__ __forceinline__ void hidden_layer(
    unsigned char* smem, const uint4* __restrict__ bfr,
    const float* __restrict__ nb, const float* __restrict__ ng, const float* __restrict__ nbe,
    const float* parC, float* parN, int tid)
{
    const int lane = tid & 31;
    const int wn   = tid >> 5;
    uint32_t* ah = reinterpret_cast<uint32_t*>(smem + AFRAG_HI);
    uint32_t* al = reinterpret_cast<uint32_t*>(smem + AFRAG_LO);
    float* red1 = reinterpret_cast<float*>(smem + RED1_OFF);
    float* red2 = reinterpret_cast<float*>(smem + RED2_OFF);
    const uint4* ah4 = reinterpret_cast<const uint4*>(ah);
    const uint4* al4 = reinterpret_cast<const uint4*>(al);

    float acc[4][4][4];
#pragma unroll
    for (int q = 0; q < 4; q++)
#pragma unroll
        for (int nt = 0; nt < 4; nt++)
#pragma unroll
            for (int r = 0; r < 4; r++) acc[q][nt][r] = 0.f;

    const uint4* bwarp = bfr + (size_t)wn * 128 + lane;   // + kt*1024 + nt*32
    constexpr int KTN = K / 16;

    uint4 B[4];
#pragma unroll
    for (int nt = 0; nt < 4; nt++)
        B[nt] = __ldg(bwarp + nt * 32);

#pragma unroll 1
    for (int kt = 0; kt < KTN; kt++) {
        uint4 Bn[4];
        if (kt + 1 < KTN) {
#pragma unroll
            for (int nt = 0; nt < 4; nt++)
                Bn[nt] = __ldg(bwarp + (size_t)(kt + 1) * 1024 + nt * 32);
        }
#pragma unroll
        for (int q = 0; q < 4; q++) {
            uint4 Ah = ah4[(q * 16 + kt) * 32 + lane];
            uint4 Al = al4[(q * 16 + kt) * 32 + lane];
#pragma unroll
            for (int nt = 0; nt < 4; nt++) {
                mma16816(acc[q][nt], Ah, B[nt].x, B[nt].y);  // hi*hi
                mma16816(acc[q][nt], Ah, B[nt].z, B[nt].w);  // hi*lo
                mma16816(acc[q][nt], Al, B[nt].x, B[nt].y);  // lo*hi
            }
        }
#pragma unroll
        for (int nt = 0; nt < 4; nt++) B[nt] = Bn[nt];
    }

    // stage NEXT layer's params (overlaps with epilogue; read next layer after barrier)
    for (int i = tid; i < 3 * NEXTN; i += 256)
        parN[i] = (i < NEXTN) ? nb[i] : (i < 2 * NEXTN ? ng[i - NEXTN] : nbe[i - 2 * NEXTN]);

    // P1: bias + per-row partial sums (bias hoisted to registers)
    const int nbase = wn * 32 + (lane & 3) * 2;
    float2 bb[4];
#pragma unroll
    for (int nt = 0; nt < 4; nt++)
        bb[nt] = *reinterpret_cast<const float2*>(parC + nbase + nt * 8);

#pragma unroll
    for (int q = 0; q < 4; q++) {
        float s1a = 0.f, s2a = 0.f, s1b = 0.f, s2b = 0.f;
#pragma unroll
        for (int nt = 0; nt < 4; nt++) {
            float y0 = acc[q][nt][0] + bb[nt].x, y1 = acc[q][nt][1] + bb[nt].y;
            float y2 = acc[q][nt][2] + bb[nt].x, y3 = acc[q][nt][3] + bb[nt].y;
            acc[q][nt][0] = y0; acc[q][nt][1] = y1;
            acc[q][nt][2] = y2; acc[q][nt][3] = y3;
            s1a += y0 + y1; s2a = fmaf(y0, y0, fmaf(y1, y1, s2a));
            s1b += y2 + y3; s2b = fmaf(y2, y2, fmaf(y3, y3, s2b));
        }
        s1a += __shfl_xor_sync(~0u, s1a, 1); s1a += __shfl_xor_sync(~0u, s1a, 2);
        s2a += __shfl_xor_sync(~0u, s2a, 1); s2a += __shfl_xor_sync(~0u, s2a, 2);
        s1b += __shfl_xor_sync(~0u, s1b, 1); s1b += __shfl_xor_sync(~0u, s1b, 2);
        s2b += __shfl_xor_sync(~0u, s2b, 1); s2b += __shfl_xor_sync(~0u, s2b, 2);
        if ((lane & 3) == 0) {
            int m0 = q * 16 + (lane >> 2);
            red1[wn * 64 + m0]     = s1a; red2[wn * 64 + m0]     = s2a;
            red1[wn * 64 + m0 + 8] = s1b; red2[wn * 64 + m0 + 8] = s2b;
        }
    }
    __syncthreads();
    if (tid < 64) {
        float t1 = 0.f, t2 = 0.f;
#pragma unroll
        for (int w = 0; w < 8; w++) { t1 += red1[w * 64 + tid]; t2 += red2[w * 64 + tid]; }
        float mean = t1 * (1.f / 256.f);
        float var  = fmaf(-mean, mean, t2 * (1.f / 256.f));
        float rstd = rsqrtf(var + EPSV);
        red1[tid] = mean; red2[tid] = rstd;
    }
    __syncthreads();

    // P3: normalize + activation + write next layer's A-fragments (gamma/beta hoisted)
    float2 gg[4], ee[4];
#pragma unroll
    for (int nt = 0; nt < 4; nt++) {
        gg[nt] = *reinterpret_cast<const float2*>(parC + 256 + nbase + nt * 8);
        ee[nt] = *reinterpret_cast<const float2*>(parC + 512 + nbase + nt * 8);
    }
#pragma unroll
    for (int q = 0; q < 4; q++) {
        int mA = q * 16 + (lane >> 2);
        float meanA = red1[mA],     rstdA = red2[mA];
        float meanB = red1[mA + 8], rstdB = red2[mA + 8];
#pragma unroll
        for (int nt = 0; nt < 4; nt++) {
            int n0 = nbase + nt * 8;
            float y0 = fmaf((acc[q][nt][0] - meanA) * rstdA, gg[nt].x, ee[nt].x);
            float y1 = fmaf((acc[q][nt][1] - meanA) * rstdA, gg[nt].y, ee[nt].y);
            float y2 = fmaf((acc[q][nt][2] - meanB) * rstdB, gg[nt].x, ee[nt].x);
            float y3 = fmaf((acc[q][nt][3] - meanB) * rstdB, gg[nt].y, ee[nt].y);
            if (ACT) { y0 = elu1(y0); y1 = elu1(y1); y2 = elu1(y2); y3 = elu1(y3); }
            int aln = ((lane >> 2) << 2) + ((n0 & 7) >> 1);
            int rA  = ((n0 & 15) >= 8) ? 2 : 0;
            int idxb = ((q * 16 + (n0 >> 4)) * 32 + aln) * 4 + rA;
            uint32_t hp0, lp0, hp1, lp1;
            split_pack(y0, y1, hp0, lp0);
            split_pack(y2, y3, hp1, lp1);
            *reinterpret_cast<uint2*>(ah + idxb) = make_uint2(hp0, hp1);
            *reinterpret_cast<uint2*>(al + idxb) = make_uint2(lp0, lp1);
        }
    }
    __syncthreads();
}

// final layer: K=256, N=32, 64 rows. Split-K: warp w<4 -> mtile w, kt 0-7;
// warp w>=4 -> mtile w-4, kt 8-15; partials combined via smem.
__device__ __forceinline__ void final_layer(
    unsigned char* smem, const uint4* __restrict__ bfr,
    const float* parC, float* __restrict__ out, int r0, int p, int tid)
{
    const int lane = tid & 31, wid = tid >> 5;
    const int m = wid & 3, kh = wid >> 2;
    const uint4* ah4 = reinterpret_cast<const uint4*>(smem + AFRAG_HI);
    const uint4* al4 = reinterpret_cast<const uint4*>(smem + AFRAG_LO);
    float* scr = reinterpret_cast<float*>(smem);       // reused after barrier

    float acc[4][4];
#pragma unroll
    for (int nt = 0; nt < 4; nt++)
#pragma unroll
        for (int r = 0; r < 4; r++) acc[nt][r] = 0.f;

#pragma unroll 1
    for (int k = 0; k < 8; k++) {
        const int kt = kh * 8 + k;
        uint4 B[4];
#pragma unroll
        for (int nt = 0; nt < 4; nt++)
            B[nt] = __ldg(&bfr[((size_t)kt * 4 + nt) * 32 + lane]);
        uint4 Ah = ah4[(m * 16 + kt) * 32 + lane];
        uint4 Al = al4[(m * 16 + kt) * 32 + lane];
#pragma unroll
        for (int nt = 0; nt < 4; nt++) {
            mma16816(acc[nt], Ah, B[nt].x, B[nt].y);
            mma16816(acc[nt], Ah, B[nt].z, B[nt].w);
            mma16816(acc[nt], Al, B[nt].x, B[nt].y);
        }
    }
    __syncthreads();     // all A-frag reads done; smem reusable
    if (kh == 1) {
        float4* s4 = reinterpret_cast<float4*>(scr) + (m * 32 + lane) * 4;
#pragma unroll
        for (int nt = 0; nt < 4; nt++)
            s4[nt] = make_float4(acc[nt][0], acc[nt][1], acc[nt][2], acc[nt][3]);
    }
    __syncthreads();
    if (kh == 1) return;

    const float4* s4 = reinterpret_cast<const float4*>(scr) + (m * 32 + lane) * 4;
#pragma unroll
    for (int nt = 0; nt < 4; nt++) {
        float4 v = s4[nt];
        acc[nt][0] += v.x; acc[nt][1] += v.y; acc[nt][2] += v.z; acc[nt][3] += v.w;
    }

    // bias + stats (warp-local: warp covers all 32 cols)
    const int nbase = (lane & 3) * 2;
    float s1a = 0.f, s2a = 0.f, s1b = 0.f, s2b = 0.f;
#pragma unroll
    for (int nt = 0; nt < 4; nt++) {
        float2 b2 = *reinterpret_cast<const float2*>(parC + nbase + nt * 8);
        float y0 = acc[nt][0] + b2.x, y1 = acc[nt][1] + b2.y;
        float y2 = acc[nt][2] + b2.x, y3 = acc[nt][3] + b2.y;
        acc[nt][0] = y0; acc[nt][1] = y1; acc[nt][2] = y2; acc[nt][3] = y3;
        s1a += y0 + y1; s2a = fmaf(y0, y0, fmaf(y1, y1, s2a));
        s1b += y2 + y3; s2b = fmaf(y2, y2, fmaf(y3, y3, s2b));
    }
    s1a += __shfl_xor_sync(~0u, s1a, 1); s1a += __shfl_xor_sync(~0u, s1a, 2);
    s2a += __shfl_xor_sync(~0u, s2a, 1); s2a += __shfl_xor_sync(~0u, s2a, 2);
    s1b += __shfl_xor_sync(~0u, s1b, 1); s1b += __shfl_xor_sync(~0u, s1b, 2);
    s2b += __shfl_xor_sync(~0u, s2b, 1); s2b += __shfl_xor_sync(~0u, s2b, 2);
    const float meanA = s1a * (1.f / 32.f);
    const float rstdA = rsqrtf(fmaf(-meanA, meanA, s2a * (1.f / 32.f)) + EPSV);
    const float meanB = s1b * (1.f / 32.f);
    const float rstdB = rsqrtf(fmaf(-meanB, meanB, s2b * (1.f / 32.f)) + EPSV);

    const int mA = m * 16 + (lane >> 2);
#pragma unroll
    for (int nt = 0; nt < 4; nt++) {
        int n0 = nbase + nt * 8;
        float2 g2 = *reinterpret_cast<const float2*>(parC + 32 + n0);
        float2 e2 = *reinterpret_cast<const float2*>(parC + 64 + n0);
        float2 o;
        o.x = fmaf((acc[nt][0] - meanA) * rstdA, g2.x, e2.x);
        o.y = fmaf((acc[nt][1] - meanA) * rstdA, g2.y, e2.y);
        *reinterpret_cast<float2*>(out + (size_t)(r0 + mA) * (NP * ACTD) + p * ACTD + n0) = o;
        o.x = fmaf((acc[nt][2] - meanB) * rstdB, g2.x, e2.x);
        o.y = fmaf((acc[nt][3] - meanB) * rstdB, g2.y, e2.y);
        *reinterpret_cast<float2*>(out + (size_t)(r0 + mA + 8) * (NP * ACTD) + p * ACTD + n0) = o;
    }
}

__global__ __launch_bounds__(256, 2)
void mlp_fused_kernel(
    const float* __restrict__ obs,
    const float* __restrict__ b1, const float* __restrict__ g1, const float* __restrict__ be1,
    const float* __restrict__ b2, const float* __restrict__ g2, const float* __restrict__ be2,
    const float* __restrict__ b3, const float* __restrict__ g3, const float* __restrict__ be3,
    const float* __restrict__ b4, const float* __restrict__ g4, const float* __restrict__ be4,
    float* __restrict__ out)
{
    extern __shared__ unsigned char smem[];
    const int tid = threadIdx.x;
    const int p   = blockIdx.y;
    const int r0  = blockIdx.x * MT;
    uint32_t* ah = reinterpret_cast<uint32_t*>(smem + AFRAG_HI);
    uint32_t* al = reinterpret_cast<uint32_t*>(smem + AFRAG_LO);
    float* par0 = reinterpret_cast<float*>(smem + PAR0_OFF);
    float* par1 = reinterpret_cast<float*>(smem + PAR1_OFF);

    // stage observation tile as split-bf16 A-fragments + layer-1 params
    {
        const int m = tid >> 2, q4 = tid & 3;
        const float* orow = obs + (size_t)(r0 + m) * OBSD + q4 * 32;
#pragma unroll
        for (int j = 0; j < 16; j++) {
            float2 v = reinterpret_cast<const float2*>(orow)[j];
            uint32_t hp, lp; split_pack(v.x, v.y, hp, lp);
            int k = q4 * 32 + j * 2;
            int aln = ((m & 7) << 2) + ((k & 7) >> 1);
            int r = (((k & 15) >= 8) ? 2 : 0) + (((m & 15) >= 8) ? 1 : 0);
            int idx = (((m >> 4) * 16 + (k >> 4)) * 32 + aln) * 4 + r;
            ah[idx] = hp; al[idx] = lp;
        }
        const float* s1 = b1 + p * HIDD;
        const float* s2 = g1 + p * HIDD;
        const float* s3 = be1 + p * HIDD;
        for (int i = tid; i < 768; i += 256)
            par0[i] = (i < 256) ? s1[i] : (i < 512 ? s2[i - 256] : s3[i - 512]);
    }
    __syncthreads();

    hidden_layer<OBSD, true, HIDD>(smem,
        reinterpret_cast<const uint4*>(g_wimg + OFF_L1 + (size_t)p * L1_BYTES),
        b2 + p * HIDD, g2 + p * HIDD, be2 + p * HIDD, par0, par1, tid);
    hidden_layer<HIDD, true, HIDD>(smem,
        reinterpret_cast<const uint4*>(g_wimg + OFF_L2 + (size_t)p * L2_BYTES),
        b3 + p * HIDD, g3 + p * HIDD, be3 + p * HIDD, par1, par0, tid);
    hidden_layer<HIDD, true, ACTD>(smem,
        reinterpret_cast<const uint4*>(g_wimg + OFF_L3 + (size_t)p * L2_BYTES),
        b4 + p * ACTD, g4 + p * ACTD, be4 + p * ACTD, par0, par1, tid);
    final_layer(smem,
        reinterpret_cast<const uint4*>(g_wimg + OFF_L4 + (size_t)p * L4_BYTES),
        par1, out, r0, p, tid);
}

// ---------------- launch ----------------
extern "C" void kernel_launch(void* const* d_in, const int* in_sizes, int n_in,
                              void* d_out, int out_size)
{
    const float* obs = (const float*)d_in[0];
    const float* W1  = (const float*)d_in[1];
    const float* b1  = (const float*)d_in[2];
    const float* g1  = (const float*)d_in[3];
    const float* be1 = (const float*)d_in[4];
    const float* W2  = (const float*)d_in[5];
    const float* b2  = (const float*)d_in[6];
    const float* g2  = (const float*)d_in[7];
    const float* be2 = (const float*)d_in[8];
    const float* W3  = (const float*)d_in[9];
    const float* b3  = (const float*)d_in[10];
    const float* g3  = (const float*)d_in[11];
    const float* be3 = (const float*)d_in[12];
    const float* W4  = (const float*)d_in[13];
    const float* b4  = (const float*)d_in[14];
    const float* g4  = (const float*)d_in[15];
    const float* be4 = (const float*)d_in[16];
    float* out = (float*)d_out;

    prep_all_kernel<<<dim3(NP, HIDD / 16, 4), 256>>>(W1, W2, W3, W4);

    cudaFuncSetAttribute(mlp_fused_kernel,
                         cudaFuncAttributeMaxDynamicSharedMemorySize, DSMEM_BYTES);
    dim3 grid(NB / MT, NP);
    mlp_fused_kernel<<<grid, 256, DSMEM_BYTES>>>(
        obs, b1, g1, be1, b2, g2, be2, b3, g3, be3, b4, g4, be4, out);
}

// round 10
// speedup vs baseline: 1.3566x; 1.3099x over previous
#include <cuda_runtime.h>
#include <cuda_fp16.h>
#include <cstdint>

#define OBSD 128
#define ACTD 32
#define HIDD 256
#define NP   64
#define NB   4096
#define MT   64
#define EPSV 1e-5f

// ---------------- SMEM layout (bytes) ----------------
#define AFRAG_HI 0          // 4 mtiles x 16 ktiles x 32 lanes x 16B = 32KB (fp16 hi only)
#define PAR0_OFF 32768      // 768 floats
#define PAR1_OFF 35840      // 768 floats
#define RED1_OFF 38912      // 8*64 floats
#define RED2_OFF 40960      // 8*64 floats
#define DSMEM_BYTES 43008

// ---------------- weight fragment image ----------------
#define L1_BYTES ((size_t)OBSD*HIDD*4)   // per-policy bytes (hi+lo fp16 = 4B/elem)
#define L2_BYTES ((size_t)HIDD*HIDD*4)
#define L4_BYTES ((size_t)HIDD*ACTD*4)
#define OFF_L1 0ull
#define OFF_L2 (OFF_L1 + 64ull*L1_BYTES)
#define OFF_L3 (OFF_L2 + 64ull*L2_BYTES)
#define OFF_L4 (OFF_L3 + 64ull*L2_BYTES)
#define WIMG_TOTAL (OFF_L4 + 64ull*L4_BYTES)

__device__ __align__(128) unsigned char g_wimg[WIMG_TOTAL];

// ---------------- helpers ----------------
__device__ __forceinline__ void mma16816(float* c, const uint4& a, uint32_t b0, uint32_t b1) {
    asm volatile(
        "mma.sync.aligned.m16n8k16.row.col.f32.f16.f16.f32 "
        "{%0,%1,%2,%3}, {%4,%5,%6,%7}, {%8,%9}, {%0,%1,%2,%3};"
        : "+f"(c[0]), "+f"(c[1]), "+f"(c[2]), "+f"(c[3])
        : "r"(a.x), "r"(a.y), "r"(a.z), "r"(a.w), "r"(b0), "r"(b1));
}

// pack two floats to f16x2 {lo=y0, hi=y1}
__device__ __forceinline__ uint32_t pack_f16(float y0, float y1) {
    uint32_t r;
    asm("cvt.rn.f16x2.f32 %0, %2, %1;" : "=r"(r) : "f"(y0), "f"(y1));
    return r;
}

// full split (prep only): hi f16 pair + residual f16 pair
__device__ __forceinline__ void split_pack_f16(float y0, float y1, uint32_t& hp, uint32_t& lp) {
    hp = pack_f16(y0, y1);
    float f0 = __half2float(__ushort_as_half((unsigned short)(hp & 0xffffu)));
    float f1 = __half2float(__ushort_as_half((unsigned short)(hp >> 16)));
    lp = pack_f16(y0 - f0, y1 - f1);
}

__device__ __forceinline__ float elu1(float y) { return y > 0.f ? y : (__expf(y) - 1.f); }

// ---------------- weight preprocess (merged, layout validated) ----------------
template<int N, int K>
__device__ __forceinline__ void prep_dev(const float* __restrict__ W, size_t off, float* tile)
{
    const int p = blockIdx.x, kt = blockIdx.y;
    if (kt >= K / 16) return;
    const int tid = threadIdx.x;
    const float4* src = reinterpret_cast<const float4*>(W + ((size_t)p * K + (size_t)kt * 16) * N);
    constexpr int NL4 = 16 * N / 4;
    for (int i = tid; i < NL4; i += 256)
        reinterpret_cast<float4*>(tile)[i] = src[i];
    __syncthreads();
    constexpr int NT = N / 8;
    uint4* dst = reinterpret_cast<uint4*>(g_wimg + off + (size_t)p * ((size_t)K * N * 4));
    for (int u = tid; u < NT * 32; u += 256) {
        int nt = u >> 5, lane = u & 31;
        int n = nt * 8 + (lane >> 2), q = (lane & 3) * 2;
        uint32_t hp[2], lp[2];
#pragma unroll
        for (int r = 0; r < 2; r++) {
            float w0 = tile[(q + 8 * r) * N + n];
            float w1 = tile[(q + 8 * r + 1) * N + n];
            split_pack_f16(w0, w1, hp[r], lp[r]);
        }
        uint4 v; v.x = hp[0]; v.y = hp[1]; v.z = lp[0]; v.w = lp[1];
        dst[((size_t)kt * NT + nt) * 32 + lane] = v;
    }
}

__global__ void prep_all_kernel(const float* __restrict__ W1, const float* __restrict__ W2,
                                const float* __restrict__ W3, const float* __restrict__ W4)
{
    __shared__ float tile[16 * HIDD];
    switch (blockIdx.z) {
        case 0: prep_dev<HIDD, OBSD>(W1, OFF_L1, tile); break;
        case 1: prep_dev<HIDD, HIDD>(W2, OFF_L2, tile); break;
        case 2: prep_dev<HIDD, HIDD>(W3, OFF_L3, tile); break;
        default: prep_dev<ACTD, HIDD>(W4, OFF_L4, tile); break;
    }
}

// ---------------- fused main kernel ----------------
// A-fragment smem layout: idx(m,k) -> uint32 slot (m in [0,64)), fp16 hi only
//   mtile=m/16, ktile=k/16, a_lane=(m%8)*4+((k%8)/2), r=2*((k%16)>=8)+((m%16)>=8)
//   idx = ((mtile*16 + ktile)*32 + a_lane)*4 + r
// 8 warps: warp wn owns cols [wn*32, wn*32+32), computes all 4 mtiles (64 rows).
// 2-term MMA: D = Ah*Whi + Ah*Wlo.

template<int K, bool ACT, int NEXTN>
__device__ __forceinline__ void hidden_layer(
    unsigned char* smem, const uint4* __restrict__ bfr,
    const float* __restrict__ nb, const float* __restrict__ ng, const float* __restrict__ nbe,
    const float* parC, float* parN, int tid)
{
    const int lane = tid & 31;
    const int wn   = tid >> 5;
    uint32_t* ah = reinterpret_cast<uint32_t*>(smem + AFRAG_HI);
    float* red1 = reinterpret_cast<float*>(smem + RED1_OFF);
    float* red2 = reinterpret_cast<float*>(smem + RED2_OFF);
    const uint4* ah4 = reinterpret_cast<const uint4*>(ah);

    float acc[4][4][4];
#pragma unroll
    for (int q = 0; q < 4; q++)
#pragma unroll
        for (int nt = 0; nt < 4; nt++)
#pragma unroll
            for (int r = 0; r < 4; r++) acc[q][nt][r] = 0.f;

    const uint4* bwarp = bfr + (size_t)wn * 128 + lane;   // + kt*1024 + nt*32
    constexpr int KTN = K / 16;

    uint4 B[4];
#pragma unroll
    for (int nt = 0; nt < 4; nt++)
        B[nt] = __ldg(bwarp + nt * 32);

#pragma unroll 1
    for (int kt = 0; kt < KTN; kt++) {
        uint4 Bn[4];
        if (kt + 1 < KTN) {
#pragma unroll
            for (int nt = 0; nt < 4; nt++)
                Bn[nt] = __ldg(bwarp + (size_t)(kt + 1) * 1024 + nt * 32);
        }
#pragma unroll
        for (int q = 0; q < 4; q++) {
            uint4 Ah = ah4[(q * 16 + kt) * 32 + lane];
#pragma unroll
            for (int nt = 0; nt < 4; nt++) {
                mma16816(acc[q][nt], Ah, B[nt].x, B[nt].y);  // A * W_hi
                mma16816(acc[q][nt], Ah, B[nt].z, B[nt].w);  // A * W_lo
            }
        }
#pragma unroll
        for (int nt = 0; nt < 4; nt++) B[nt] = Bn[nt];
    }

    // stage NEXT layer's params (overlaps epilogue)
    for (int i = tid; i < 3 * NEXTN; i += 256)
        parN[i] = (i < NEXTN) ? nb[i] : (i < 2 * NEXTN ? ng[i - NEXTN] : nbe[i - 2 * NEXTN]);

    // P1: bias + per-row partial sums (bias hoisted)
    const int nbase = wn * 32 + (lane & 3) * 2;
    float2 bb[4];
#pragma unroll
    for (int nt = 0; nt < 4; nt++)
        bb[nt] = *reinterpret_cast<const float2*>(parC + nbase + nt * 8);

#pragma unroll
    for (int q = 0; q < 4; q++) {
        float s1a = 0.f, s2a = 0.f, s1b = 0.f, s2b = 0.f;
#pragma unroll
        for (int nt = 0; nt < 4; nt++) {
            float y0 = acc[q][nt][0] + bb[nt].x, y1 = acc[q][nt][1] + bb[nt].y;
            float y2 = acc[q][nt][2] + bb[nt].x, y3 = acc[q][nt][3] + bb[nt].y;
            acc[q][nt][0] = y0; acc[q][nt][1] = y1;
            acc[q][nt][2] = y2; acc[q][nt][3] = y3;
            s1a += y0 + y1; s2a = fmaf(y0, y0, fmaf(y1, y1, s2a));
            s1b += y2 + y3; s2b = fmaf(y2, y2, fmaf(y3, y3, s2b));
        }
        s1a += __shfl_xor_sync(~0u, s1a, 1); s1a += __shfl_xor_sync(~0u, s1a, 2);
        s2a += __shfl_xor_sync(~0u, s2a, 1); s2a += __shfl_xor_sync(~0u, s2a, 2);
        s1b += __shfl_xor_sync(~0u, s1b, 1); s1b += __shfl_xor_sync(~0u, s1b, 2);
        s2b += __shfl_xor_sync(~0u, s2b, 1); s2b += __shfl_xor_sync(~0u, s2b, 2);
        if ((lane & 3) == 0) {
            int m0 = q * 16 + (lane >> 2);
            red1[wn * 64 + m0]     = s1a; red2[wn * 64 + m0]     = s2a;
            red1[wn * 64 + m0 + 8] = s1b; red2[wn * 64 + m0 + 8] = s2b;
        }
    }
    __syncthreads();
    if (tid < 64) {
        float t1 = 0.f, t2 = 0.f;
#pragma unroll
        for (int w = 0; w < 8; w++) { t1 += red1[w * 64 + tid]; t2 += red2[w * 64 + tid]; }
        float mean = t1 * (1.f / 256.f);
        float var  = fmaf(-mean, mean, t2 * (1.f / 256.f));
        float rstd = rsqrtf(var + EPSV);
        red1[tid] = mean; red2[tid] = rstd;
    }
    __syncthreads();

    // P3: normalize + activation + write next layer's A (fp16 hi only)
    float2 gg[4], ee[4];
#pragma unroll
    for (int nt = 0; nt < 4; nt++) {
        gg[nt] = *reinterpret_cast<const float2*>(parC + 256 + nbase + nt * 8);
        ee[nt] = *reinterpret_cast<const float2*>(parC + 512 + nbase + nt * 8);
    }
#pragma unroll
    for (int q = 0; q < 4; q++) {
        int mA = q * 16 + (lane >> 2);
        float meanA = red1[mA],     rstdA = red2[mA];
        float meanB = red1[mA + 8], rstdB = red2[mA + 8];
#pragma unroll
        for (int nt = 0; nt < 4; nt++) {
            int n0 = nbase + nt * 8;
            float y0 = fmaf((acc[q][nt][0] - meanA) * rstdA, gg[nt].x, ee[nt].x);
            float y1 = fmaf((acc[q][nt][1] - meanA) * rstdA, gg[nt].y, ee[nt].y);
            float y2 = fmaf((acc[q][nt][2] - meanB) * rstdB, gg[nt].x, ee[nt].x);
            float y3 = fmaf((acc[q][nt][3] - meanB) * rstdB, gg[nt].y, ee[nt].y);
            if (ACT) { y0 = elu1(y0); y1 = elu1(y1); y2 = elu1(y2); y3 = elu1(y3); }
            int aln = ((lane >> 2) << 2) + ((n0 & 7) >> 1);
            int rA  = ((n0 & 15) >= 8) ? 2 : 0;
            int idxb = ((q * 16 + (n0 >> 4)) * 32 + aln) * 4 + rA;
            *reinterpret_cast<uint2*>(ah + idxb) =
                make_uint2(pack_f16(y0, y1), pack_f16(y2, y3));
        }
    }
    __syncthreads();
}

// final layer: K=256, N=32, 64 rows. Split-K across warp halves.
__device__ __forceinline__ void final_layer(
    unsigned char* smem, const uint4* __restrict__ bfr,
    const float* parC, float* __restrict__ out, int r0, int p, int tid)
{
    const int lane = tid & 31, wid = tid >> 5;
    const int m = wid & 3, kh = wid >> 2;
    const uint4* ah4 = reinterpret_cast<const uint4*>(smem + AFRAG_HI);
    float* scr = reinterpret_cast<float*>(smem);       // reused after barrier

    float acc[4][4];
#pragma unroll
    for (int nt = 0; nt < 4; nt++)
#pragma unroll
        for (int r = 0; r < 4; r++) acc[nt][r] = 0.f;

#pragma unroll 1
    for (int k = 0; k < 8; k++) {
        const int kt = kh * 8 + k;
        uint4 B[4];
#pragma unroll
        for (int nt = 0; nt < 4; nt++)
            B[nt] = __ldg(&bfr[((size_t)kt * 4 + nt) * 32 + lane]);
        uint4 Ah = ah4[(m * 16 + kt) * 32 + lane];
#pragma unroll
        for (int nt = 0; nt < 4; nt++) {
            mma16816(acc[nt], Ah, B[nt].x, B[nt].y);
            mma16816(acc[nt], Ah, B[nt].z, B[nt].w);
        }
    }
    __syncthreads();     // all A-frag reads done; smem reusable
    if (kh == 1) {
        float4* s4 = reinterpret_cast<float4*>(scr) + (m * 32 + lane) * 4;
#pragma unroll
        for (int nt = 0; nt < 4; nt++)
            s4[nt] = make_float4(acc[nt][0], acc[nt][1], acc[nt][2], acc[nt][3]);
    }
    __syncthreads();
    if (kh == 1) return;

    const float4* s4 = reinterpret_cast<const float4*>(scr) + (m * 32 + lane) * 4;
#pragma unroll
    for (int nt = 0; nt < 4; nt++) {
        float4 v = s4[nt];
        acc[nt][0] += v.x; acc[nt][1] += v.y; acc[nt][2] += v.z; acc[nt][3] += v.w;
    }

    // bias + stats (warp-local: warp covers all 32 cols)
    const int nbase = (lane & 3) * 2;
    float s1a = 0.f, s2a = 0.f, s1b = 0.f, s2b = 0.f;
#pragma unroll
    for (int nt = 0; nt < 4; nt++) {
        float2 b2 = *reinterpret_cast<const float2*>(parC + nbase + nt * 8);
        float y0 = acc[nt][0] + b2.x, y1 = acc[nt][1] + b2.y;
        float y2 = acc[nt][2] + b2.x, y3 = acc[nt][3] + b2.y;
        acc[nt][0] = y0; acc[nt][1] = y1; acc[nt][2] = y2; acc[nt][3] = y3;
        s1a += y0 + y1; s2a = fmaf(y0, y0, fmaf(y1, y1, s2a));
        s1b += y2 + y3; s2b = fmaf(y2, y2, fmaf(y3, y3, s2b));
    }
    s1a += __shfl_xor_sync(~0u, s1a, 1); s1a += __shfl_xor_sync(~0u, s1a, 2);
    s2a += __shfl_xor_sync(~0u, s2a, 1); s2a += __shfl_xor_sync(~0u, s2a, 2);
    s1b += __shfl_xor_sync(~0u, s1b, 1); s1b += __shfl_xor_sync(~0u, s1b, 2);
    s2b += __shfl_xor_sync(~0u, s2b, 1); s2b += __shfl_xor_sync(~0u, s2b, 2);
    const float meanA = s1a * (1.f / 32.f);
    const float rstdA = rsqrtf(fmaf(-meanA, meanA, s2a * (1.f / 32.f)) + EPSV);
    const float meanB = s1b * (1.f / 32.f);
    const float rstdB = rsqrtf(fmaf(-meanB, meanB, s2b * (1.f / 32.f)) + EPSV);

    const int mA = m * 16 + (lane >> 2);
#pragma unroll
    for (int nt = 0; nt < 4; nt++) {
        int n0 = nbase + nt * 8;
        float2 g2 = *reinterpret_cast<const float2*>(parC + 32 + n0);
        float2 e2 = *reinterpret_cast<const float2*>(parC + 64 + n0);
        float2 o;
        o.x = fmaf((acc[nt][0] - meanA) * rstdA, g2.x, e2.x);
        o.y = fmaf((acc[nt][1] - meanA) * rstdA, g2.y, e2.y);
        *reinterpret_cast<float2*>(out + (size_t)(r0 + mA) * (NP * ACTD) + p * ACTD + n0) = o;
        o.x = fmaf((acc[nt][2] - meanB) * rstdB, g2.x, e2.x);
        o.y = fmaf((acc[nt][3] - meanB) * rstdB, g2.y, e2.y);
        *reinterpret_cast<float2*>(out + (size_t)(r0 + mA + 8) * (NP * ACTD) + p * ACTD + n0) = o;
    }
}

__global__ __launch_bounds__(256, 2)
void mlp_fused_kernel(
    const float* __restrict__ obs,
    const float* __restrict__ b1, const float* __restrict__ g1, const float* __restrict__ be1,
    const float* __restrict__ b2, const float* __restrict__ g2, const float* __restrict__ be2,
    const float* __restrict__ b3, const float* __restrict__ g3, const float* __restrict__ be3,
    const float* __restrict__ b4, const float* __restrict__ g4, const float* __restrict__ be4,
    float* __restrict__ out)
{
    extern __shared__ unsigned char smem[];
    const int tid = threadIdx.x;
    const int p   = blockIdx.y;
    const int r0  = blockIdx.x * MT;
    uint32_t* ah = reinterpret_cast<uint32_t*>(smem + AFRAG_HI);
    float* par0 = reinterpret_cast<float*>(smem + PAR0_OFF);
    float* par1 = reinterpret_cast<float*>(smem + PAR1_OFF);

    // stage observation tile as fp16 A-fragments + layer-1 params
    {
        const int m = tid >> 2, q4 = tid & 3;
        const float* orow = obs + (size_t)(r0 + m) * OBSD + q4 * 32;
#pragma unroll
        for (int j = 0; j < 16; j++) {
            float2 v = reinterpret_cast<const float2*>(orow)[j];
            int k = q4 * 32 + j * 2;
            int aln = ((m & 7) << 2) + ((k & 7) >> 1);
            int r = (((k & 15) >= 8) ? 2 : 0) + (((m & 15) >= 8) ? 1 : 0);
            int idx = (((m >> 4) * 16 + (k >> 4)) * 32 + aln) * 4 + r;
            ah[idx] = pack_f16(v.x, v.y);
        }
        const float* s1 = b1 + p * HIDD;
        const float* s2 = g1 + p * HIDD;
        const float* s3 = be1 + p * HIDD;
        for (int i = tid; i < 768; i += 256)
            par0[i] = (i < 256) ? s1[i] : (i < 512 ? s2[i - 256] : s3[i - 512]);
    }
    __syncthreads();

    hidden_layer<OBSD, true, HIDD>(smem,
        reinterpret_cast<const uint4*>(g_wimg + OFF_L1 + (size_t)p * L1_BYTES),
        b2 + p * HIDD, g2 + p * HIDD, be2 + p * HIDD, par0, par1, tid);
    hidden_layer<HIDD, true, HIDD>(smem,
        reinterpret_cast<const uint4*>(g_wimg + OFF_L2 + (size_t)p * L2_BYTES),
        b3 + p * HIDD, g3 + p * HIDD, be3 + p * HIDD, par1, par0, tid);
    hidden_layer<HIDD, true, ACTD>(smem,
        reinterpret_cast<const uint4*>(g_wimg + OFF_L3 + (size_t)p * L2_BYTES),
        b4 + p * ACTD, g4 + p * ACTD, be4 + p * ACTD, par0, par1, tid);
    final_layer(smem,
        reinterpret_cast<const uint4*>(g_wimg + OFF_L4 + (size_t)p * L4_BYTES),
        par1, out, r0, p, tid);
}

// ---------------- launch ----------------
extern "C" void kernel_launch(void* const* d_in, const int* in_sizes, int n_in,
                              void* d_out, int out_size)
{
    const float* obs = (const float*)d_in[0];
    const float* W1  = (const float*)d_in[1];
    const float* b1  = (const float*)d_in[2];
    const float* g1  = (const float*)d_in[3];
    const float* be1 = (const float*)d_in[4];
    const float* W2  = (const float*)d_in[5];
    const float* b2  = (const float*)d_in[6];
    const float* g2  = (const float*)d_in[7];
    const float* be2 = (const float*)d_in[8];
    const float* W3  = (const float*)d_in[9];
    const float* b3  = (const float*)d_in[10];
    const float* g3  = (const float*)d_in[11];
    const float* be3 = (const float*)d_in[12];
    const float* W4  = (const float*)d_in[13];
    const float* b4  = (const float*)d_in[14];
    const float* g4  = (const float*)d_in[15];
    const float* be4 = (const float*)d_in[16];
    float* out = (float*)d_out;

    prep_all_kernel<<<dim3(NP, HIDD / 16, 4), 256>>>(W1, W2, W3, W4);

    cudaFuncSetAttribute(mlp_fused_kernel,
                         cudaFuncAttributeMaxDynamicSharedMemorySize, DSMEM_BYTES);
    dim3 grid(NB / MT, NP);
    mlp_fused_kernel<<<grid, 256, DSMEM_BYTES>>>(
        obs, b1, g1, be1, b2, g2, be2, b3, g3, be3, b4, g4, be4, out);
}